// round 10
// baseline (speedup 1.0000x reference)
#include <cuda_runtime.h>
#include <cuda_bf16.h>

// DilatedAttention: b=2,h=16,s=8192,d=64; groups (w,r)=(4,1),(8,2),(16,4).
// TWO 16-position superblocks per 256-thread CTA (tid>>7 selects superblock;
// per-superblock logic identical to the proven 128-thread version on tid&127).
// q/k: XOR-swizzled smem, staged cp.async.cg.
// v:   LINEAR smem, ONE 8KB TMA bulk + mbarrier, wait deferred past dot phase.
// AV:  warp-per-window mapping, v rows register-cached.
// Warps/SM held at the measured optimum (48): __launch_bounds__(256, 6).

#define TPB 256

__device__ __forceinline__ int rswz(int r) { return (r ^ (r >> 3)) & 7; }

__device__ __forceinline__ void cpasync16(void* smem_dst, const void* gmem_src) {
    unsigned s = (unsigned)__cvta_generic_to_shared(smem_dst);
    asm volatile("cp.async.cg.shared.global [%0], [%1], 16;\n" :: "r"(s), "l"(gmem_src));
}

__global__ __launch_bounds__(TPB, 6)
void dilated_attn_kernel(const float* __restrict__ q,
                         const float* __restrict__ k,
                         const float* __restrict__ v,
                         const float* __restrict__ alpha,
                         float* __restrict__ out)
{
    __shared__ float4 qs[32 * 16];   // XOR-swizzled, rows 0..31 (2 superblocks)
    __shared__ float4 ks[32 * 16];   // XOR-swizzled
    __shared__ float4 vs[32 * 16];   // LINEAR
    __shared__ __align__(16) float ps[2 * 112];  // per-superblock probs
    __shared__ float  wmix[3];
    __shared__ __align__(8) unsigned long long mbar;

    const int tid = threadIdx.x;
    const size_t base = (size_t)blockIdx.x * 2048;   // floats (2 superblocks)

    const unsigned mb = (unsigned)__cvta_generic_to_shared(&mbar);

    if (tid == 0) {
        asm volatile("mbarrier.init.shared.b64 [%0], 1;" :: "r"(mb) : "memory");
        asm volatile("fence.proxy.async.shared::cta;" ::: "memory");
    }
    __syncthreads();   // mbar init visible to all + to TMA

    // ---- v tiles (both superblocks, contiguous): ONE 8KB TMA bulk copy ----
    if (tid == 0) {
        unsigned vdst = (unsigned)__cvta_generic_to_shared(vs);
        asm volatile("mbarrier.arrive.expect_tx.shared.b64 _, [%0], %1;"
                     :: "r"(mb), "r"(8192u) : "memory");
        asm volatile("cp.async.bulk.shared::cta.global.mbarrier::complete_tx::bytes "
                     "[%0], [%1], %2, [%3];"
                     :: "r"(vdst), "l"(v + base), "r"(8192u), "r"(mb) : "memory");
    }

    // ---- q,k tiles (32 rows) into XOR-swizzled smem via cp.async ----
    {
        const float4* q4 = (const float4*)(q + base);
        const float4* k4 = (const float4*)(k + base);
        #pragma unroll
        for (int i = 0; i < 2; i++) {
            int idx = tid + i * TPB;               // 0..511
            int r   = idx >> 4;                    // row 0..31
            int c4  = idx & 15;
            int d   = r * 16 + (c4 ^ rswz(r & 15));
            cpasync16(&qs[d], &q4[idx]);
            cpasync16(&ks[d], &k4[idx]);
        }
        asm volatile("cp.async.commit_group;\n");
    }

    if (tid == 32) {   // mixing weights softmax(alpha) (not the TMA-issuing thread)
        float a0 = __ldg(alpha + 0), a1 = __ldg(alpha + 1), a2 = __ldg(alpha + 2);
        float am = fmaxf(a0, fmaxf(a1, a2));
        float e0 = __expf(a0 - am), e1 = __expf(a1 - am), e2 = __expf(a2 - am);
        float wi = 1.0f / (e0 + e1 + e2);
        wmix[0] = e0 * wi; wmix[1] = e1 * wi; wmix[2] = e2 * wi;
    }

    asm volatile("cp.async.wait_group 0;\n");
    __syncthreads();

    const int sb = tid >> 7;                 // superblock 0/1
    const int t  = tid & 127;                // role within superblock
    const float4* qsb = qs + sb * 256;       // 16 rows * 16 cols
    const float4* ksb = ks + sb * 256;
    const float4* vsb = vs + sb * 256;
    float* psb = ps + sb * 112;

    // ---- dot phase: quad softmax over 4 keys, scalar ps store ----
    {
        const int warp = t >> 5;
        if (warp < 3) {                       // g0 (warps 0,1) and g1 (warp 2)
            int qrow, krow, pslot;
            const int kj = t & 3;
            if (warp < 2) {                   // g0: 16 instances x 4 keys
                int inst = t >> 2;
                qrow  = inst;
                krow  = (inst & ~3) | kj;
                pslot = t;
            } else {                          // g1: 8 instances (even positions)
                int l = t - 64;
                int inst = l >> 2;
                int win = inst >> 2, qi = inst & 3;
                qrow  = win * 8 + qi * 2;
                krow  = win * 8 + kj * 2;
                pslot = 64 + l;
            }
            const float4* qr = qsb + qrow * 16;
            const float4* kr = ksb + krow * 16;
            const int gq = rswz(qrow), gk = rswz(krow);

            float acc = 0.0f;
            #pragma unroll
            for (int c = 0; c < 16; c++) {
                float4 a = qr[c ^ gq];        // same logical column c for q and k
                float4 b = kr[c ^ gk];
                acc = fmaf(a.x, b.x, acc);
                acc = fmaf(a.y, b.y, acc);
                acc = fmaf(a.z, b.z, acc);
                acc = fmaf(a.w, b.w, acc);
            }
            acc *= 0.125f;

            float m = acc;
            m = fmaxf(m, __shfl_xor_sync(0xFFFFFFFFu, m, 1));
            m = fmaxf(m, __shfl_xor_sync(0xFFFFFFFFu, m, 2));
            float e = __expf(acc - m);
            float s = e;
            s += __shfl_xor_sync(0xFFFFFFFFu, s, 1);
            s += __shfl_xor_sync(0xFFFFFFFFu, s, 2);
            psb[pslot] = e / s;
        } else {                              // g2: 16 dots, d-split across 32 lanes
            int l    = t - 96;
            int h    = l >> 4;                // d-half
            int idx  = l & 15;
            int inst = idx >> 2, kj = idx & 3;
            int qrow = inst * 4, krow = kj * 4;
            const float4* qr = qsb + qrow * 16;
            const float4* kr = ksb + krow * 16;
            const int gq = rswz(qrow), gk = rswz(krow);
            const int cbase = 8 * h, coff = 2 * h;   // stagger halves -> conflict-free

            float acc = 0.0f;
            #pragma unroll
            for (int c = 0; c < 8; c++) {
                int col = cbase + ((c + coff) & 7);  // same logical col for q and k
                float4 a = qr[col ^ gq];
                float4 b = kr[col ^ gk];
                acc = fmaf(a.x, b.x, acc);
                acc = fmaf(a.y, b.y, acc);
                acc = fmaf(a.z, b.z, acc);
                acc = fmaf(a.w, b.w, acc);
            }
            acc += __shfl_xor_sync(0xFFFFFFFFu, acc, 16);   // combine d-halves
            acc *= 0.125f;

            float m = acc;
            m = fmaxf(m, __shfl_xor_sync(0xFFFFFFFFu, m, 1));
            m = fmaxf(m, __shfl_xor_sync(0xFFFFFFFFu, m, 2));
            float e = __expf(acc - m);
            float s = e;
            s += __shfl_xor_sync(0xFFFFFFFFu, s, 1);
            s += __shfl_xor_sync(0xFFFFFFFFu, s, 2);
            if (h == 0) psb[96 + idx] = e / s;
        }
    }
    __syncthreads();

    // ---- wait for v TMA (usually long done) ----
    asm volatile(
        "{\n\t.reg .pred P;\n"
        "WAITLP_%=:\n\t"
        "mbarrier.try_wait.parity.acquire.cta.shared::cta.b64 P, [%0], 0, 0x989680;\n\t"
        "@!P bra WAITLP_%=;\n\t}"
        :: "r"(mb) : "memory");

    // ---- AV phase: warp (t>>5) owns window positions {4w..4w+3} in its sb ----
    {
        const int w    = t >> 5;
        const int lane = t & 31;
        const int c4   = lane & 15;
        const int pp   = lane >> 4;          // 0/1
        const float W0 = wmix[0], W1 = wmix[1], W2 = wmix[2];

        const int pos_e = 4 * w + 2 * pp;    // even position handled by this thread
        const int pos_o = pos_e + 1;         // odd position

        float4* o4 = (float4*)(out + base + sb * 1024);

        float ax, ay, az, aw;                // accumulator for pos_e
        {
            // g0 window rows, shared by the whole warp (broadcast loads)
            float4 R0 = vsb[(4 * w + 0) * 16 + c4];
            float4 R1 = vsb[(4 * w + 1) * 16 + c4];
            float4 R2 = vsb[(4 * w + 2) * 16 + c4];
            float4 R3 = vsb[(4 * w + 3) * 16 + c4];

            // ---- odd position: group0 only; store immediately, free regs ----
            {
                float4 pa = *(const float4*)(psb + 4 * pos_o);
                float sx = pa.x * R0.x, sy = pa.x * R0.y, sz = pa.x * R0.z, sw = pa.x * R0.w;
                sx = fmaf(pa.y, R1.x, sx); sy = fmaf(pa.y, R1.y, sy);
                sz = fmaf(pa.y, R1.z, sz); sw = fmaf(pa.y, R1.w, sw);
                sx = fmaf(pa.z, R2.x, sx); sy = fmaf(pa.z, R2.y, sy);
                sz = fmaf(pa.z, R2.z, sz); sw = fmaf(pa.z, R2.w, sw);
                sx = fmaf(pa.w, R3.x, sx); sy = fmaf(pa.w, R3.y, sy);
                sz = fmaf(pa.w, R3.z, sz); sw = fmaf(pa.w, R3.w, sw);
                float4 r; r.x = W0 * sx; r.y = W0 * sy; r.z = W0 * sz; r.w = W0 * sw;
                __stcs(&o4[pos_o * 16 + c4], r);
            }

            // ---- even position g0 ----
            {
                float4 pa = *(const float4*)(psb + 4 * pos_e);
                float sx = pa.x * R0.x, sy = pa.x * R0.y, sz = pa.x * R0.z, sw = pa.x * R0.w;
                sx = fmaf(pa.y, R1.x, sx); sy = fmaf(pa.y, R1.y, sy);
                sz = fmaf(pa.y, R1.z, sz); sw = fmaf(pa.y, R1.w, sw);
                sx = fmaf(pa.z, R2.x, sx); sy = fmaf(pa.z, R2.y, sy);
                sz = fmaf(pa.z, R2.z, sz); sw = fmaf(pa.z, R2.w, sw);
                sx = fmaf(pa.w, R3.x, sx); sy = fmaf(pa.w, R3.y, sy);
                sz = fmaf(pa.w, R3.z, sz); sw = fmaf(pa.w, R3.w, sw);
                ax = W0 * sx; ay = W0 * sy; az = W0 * sz; aw = W0 * sw;
            }

            // ---- even position g1: rows 8*win + {0,2,4,6}; R0/R2 cover two ----
            {
                const int win   = w >> 1;
                const int inst1 = win * 4 + ((pos_e >> 1) & 3);
                float4 pb = *(const float4*)(psb + 64 + 4 * inst1);
                const int eoff = (w & 1) ? 0 : 4;   // extra rows: odd w -> {0,2}, even w -> {4,6}
                float4 E0 = vsb[(8 * win + eoff + 0) * 16 + c4];
                float4 E1 = vsb[(8 * win + eoff + 2) * 16 + c4];
                float c0, c1, c2, c3;               // j->register map
                if ((w & 1) == 0) { c0 = pb.x; c1 = pb.y; c2 = pb.z; c3 = pb.w; }
                else              { c2 = pb.x; c3 = pb.y; c0 = pb.z; c1 = pb.w; }
                float sx = c0 * R0.x, sy = c0 * R0.y, sz = c0 * R0.z, sw = c0 * R0.w;
                sx = fmaf(c1, R2.x, sx); sy = fmaf(c1, R2.y, sy);
                sz = fmaf(c1, R2.z, sz); sw = fmaf(c1, R2.w, sw);
                sx = fmaf(c2, E0.x, sx); sy = fmaf(c2, E0.y, sy);
                sz = fmaf(c2, E0.z, sz); sw = fmaf(c2, E0.w, sw);
                sx = fmaf(c3, E1.x, sx); sy = fmaf(c3, E1.y, sy);
                sz = fmaf(c3, E1.z, sz); sw = fmaf(c3, E1.w, sw);
                ax = fmaf(W1, sx, ax); ay = fmaf(W1, sy, ay);
                az = fmaf(W1, sz, az); aw = fmaf(W1, sw, aw);
            }
        }   // R0..R3 dead here

        // ---- even position g2 (only pp==0, pos_e == 4w): rows {0,4,8,12} ----
        if (pp == 0) {
            float4 pc = *(const float4*)(psb + 96 + 4 * w);
            float4 G0 = vsb[ 0 * 16 + c4];
            float4 G1 = vsb[ 4 * 16 + c4];
            float4 G2 = vsb[ 8 * 16 + c4];
            float4 G3 = vsb[12 * 16 + c4];
            float sx = pc.x * G0.x, sy = pc.x * G0.y, sz = pc.x * G0.z, sw = pc.x * G0.w;
            sx = fmaf(pc.y, G1.x, sx); sy = fmaf(pc.y, G1.y, sy);
            sz = fmaf(pc.y, G1.z, sz); sw = fmaf(pc.y, G1.w, sw);
            sx = fmaf(pc.z, G2.x, sx); sy = fmaf(pc.z, G2.y, sy);
            sz = fmaf(pc.z, G2.z, sz); sw = fmaf(pc.z, G2.w, sw);
            sx = fmaf(pc.w, G3.x, sx); sy = fmaf(pc.w, G3.y, sy);
            sz = fmaf(pc.w, G3.z, sz); sw = fmaf(pc.w, G3.w, sw);
            ax = fmaf(W2, sx, ax); ay = fmaf(W2, sy, ay);
            az = fmaf(W2, sz, az); aw = fmaf(W2, sw, aw);
        }

        float4 r; r.x = ax; r.y = ay; r.z = az; r.w = aw;
        __stcs(&o4[pos_e * 16 + c4], r);
    }
}

extern "C" void kernel_launch(void* const* d_in, const int* in_sizes, int n_in,
                              void* d_out, int out_size)
{
    const float* q     = (const float*)d_in[0];
    const float* k     = (const float*)d_in[1];
    const float* v     = (const float*)d_in[2];
    const float* alpha = (const float*)d_in[3];
    float* out         = (float*)d_out;

    int n_ctas = in_sizes[0] / 2048;   // 8192 (2 superblocks per CTA)
    dilated_attn_kernel<<<n_ctas, TPB>>>(q, k, v, alpha, out);
}

// round 11
// speedup vs baseline: 1.0613x; 1.0613x over previous
#include <cuda_runtime.h>
#include <cuda_bf16.h>

// DilatedAttention: b=2,h=16,s=8192,d=64; groups (w,r)=(4,1),(8,2),(16,4).
// PERSISTENT kernel: 1216 CTAs x 128 threads, grid-stride over 16384
// 16-position superblocks, DOUBLE-BUFFERED staging (prefetch tile i+1 during
// compute of tile i). q/k XOR-swizzled smem, v linear; one cp.async
// commit-group per tile. Dot/AV phase logic identical to the validated R9.

#define TPB   128
#define GRID  1216   // 152 SMs x 8 CTAs

__device__ __forceinline__ int rswz(int r) { return (r ^ (r >> 3)) & 7; }

__device__ __forceinline__ void cpasync16(void* smem_dst, const void* gmem_src) {
    unsigned s = (unsigned)__cvta_generic_to_shared(smem_dst);
    asm volatile("cp.async.cg.shared.global [%0], [%1], 16;\n" :: "r"(s), "l"(gmem_src));
}

__global__ __launch_bounds__(TPB, 8)
void dilated_attn_kernel(const float* __restrict__ q,
                         const float* __restrict__ k,
                         const float* __restrict__ v,
                         const float* __restrict__ alpha,
                         float* __restrict__ out,
                         int n_tiles)
{
    __shared__ float4 qs[2][256];    // XOR-swizzled
    __shared__ float4 ks[2][256];    // XOR-swizzled
    __shared__ float4 vs[2][256];    // LINEAR
    __shared__ __align__(16) float ps[112];  // probs: g0 [0,64), g1 [64,96), g2 [96,112)
    __shared__ float  wmix[3];

    const int tid = threadIdx.x;

    if (tid == 0) {   // mixing weights softmax(alpha), once per CTA
        float a0 = __ldg(alpha + 0), a1 = __ldg(alpha + 1), a2 = __ldg(alpha + 2);
        float am = fmaxf(a0, fmaxf(a1, a2));
        float e0 = __expf(a0 - am), e1 = __expf(a1 - am), e2 = __expf(a2 - am);
        float wi = 1.0f / (e0 + e1 + e2);
        wmix[0] = e0 * wi; wmix[1] = e1 * wi; wmix[2] = e2 * wi;
    }

    // per-thread staging geometry (constant across tiles)
    const int i0 = tid,        r0 = i0 >> 4, c0 = i0 & 15, d0 = r0 * 16 + (c0 ^ rswz(r0));
    const int i1 = tid + TPB,  r1 = i1 >> 4, c1 = i1 & 15, d1 = r1 * 16 + (c1 ^ rswz(r1));

    int tile = blockIdx.x;
    int cur  = 0;

    // ---- prologue: issue tile0's loads into buffer 0 ----
    if (tile < n_tiles) {
        const float4* q4 = (const float4*)q + (size_t)tile * 256;
        const float4* k4 = (const float4*)k + (size_t)tile * 256;
        const float4* v4 = (const float4*)v + (size_t)tile * 256;
        cpasync16(&qs[0][d0], &q4[i0]);  cpasync16(&qs[0][d1], &q4[i1]);
        cpasync16(&ks[0][d0], &k4[i0]);  cpasync16(&ks[0][d1], &k4[i1]);
        cpasync16(&vs[0][i0], &v4[i0]);  cpasync16(&vs[0][i1], &v4[i1]);
        asm volatile("cp.async.commit_group;\n");
    }

    for (; tile < n_tiles; tile += GRID) {
        asm volatile("cp.async.wait_group 0;\n");
        __syncthreads();   // tile's data visible to all; prev AV fully done

        // ---- prefetch next tile into the other buffer (overlaps compute) ----
        {
            int next = tile + GRID;
            if (next < n_tiles) {
                int nb = cur ^ 1;
                const float4* q4 = (const float4*)q + (size_t)next * 256;
                const float4* k4 = (const float4*)k + (size_t)next * 256;
                const float4* v4 = (const float4*)v + (size_t)next * 256;
                cpasync16(&qs[nb][d0], &q4[i0]);  cpasync16(&qs[nb][d1], &q4[i1]);
                cpasync16(&ks[nb][d0], &k4[i0]);  cpasync16(&ks[nb][d1], &k4[i1]);
                cpasync16(&vs[nb][i0], &v4[i0]);  cpasync16(&vs[nb][i1], &v4[i1]);
                asm volatile("cp.async.commit_group;\n");
            }
        }

        const float4* qsb = qs[cur];
        const float4* ksb = ks[cur];
        const float4* vsb = vs[cur];

        // ---- dot phase: quad softmax over 4 keys, scalar ps store ----
        {
            const int warp = tid >> 5;
            if (warp < 3) {                       // g0 (warps 0,1) and g1 (warp 2)
                int qrow, krow, pslot;
                const int kj = tid & 3;
                if (warp < 2) {                   // g0: 16 instances x 4 keys
                    int inst = tid >> 2;
                    qrow  = inst;
                    krow  = (inst & ~3) | kj;
                    pslot = tid;
                } else {                          // g1: 8 instances (even positions)
                    int l = tid - 64;
                    int inst = l >> 2;
                    int win = inst >> 2, qi = inst & 3;
                    qrow  = win * 8 + qi * 2;
                    krow  = win * 8 + kj * 2;
                    pslot = 64 + l;
                }
                const float4* qr = qsb + qrow * 16;
                const float4* kr = ksb + krow * 16;
                const int gq = rswz(qrow), gk = rswz(krow);

                float acc = 0.0f;
                #pragma unroll
                for (int c = 0; c < 16; c++) {
                    float4 a = qr[c ^ gq];        // same logical column c for q and k
                    float4 b = kr[c ^ gk];
                    acc = fmaf(a.x, b.x, acc);
                    acc = fmaf(a.y, b.y, acc);
                    acc = fmaf(a.z, b.z, acc);
                    acc = fmaf(a.w, b.w, acc);
                }
                acc *= 0.125f;

                float m = acc;
                m = fmaxf(m, __shfl_xor_sync(0xFFFFFFFFu, m, 1));
                m = fmaxf(m, __shfl_xor_sync(0xFFFFFFFFu, m, 2));
                float e = __expf(acc - m);
                float s = e;
                s += __shfl_xor_sync(0xFFFFFFFFu, s, 1);
                s += __shfl_xor_sync(0xFFFFFFFFu, s, 2);
                ps[pslot] = e / s;
            } else {                              // g2: 16 dots, d-split across 32 lanes
                int l    = tid - 96;
                int h    = l >> 4;                // d-half
                int idx  = l & 15;
                int inst = idx >> 2, kj = idx & 3;
                int qrow = inst * 4, krow = kj * 4;
                const float4* qr = qsb + qrow * 16;
                const float4* kr = ksb + krow * 16;
                const int gq = rswz(qrow), gk = rswz(krow);
                const int cbase = 8 * h, coff = 2 * h;   // stagger halves -> conflict-free

                float acc = 0.0f;
                #pragma unroll
                for (int c = 0; c < 8; c++) {
                    int col = cbase + ((c + coff) & 7);  // same logical col for q and k
                    float4 a = qr[col ^ gq];
                    float4 b = kr[col ^ gk];
                    acc = fmaf(a.x, b.x, acc);
                    acc = fmaf(a.y, b.y, acc);
                    acc = fmaf(a.z, b.z, acc);
                    acc = fmaf(a.w, b.w, acc);
                }
                acc += __shfl_xor_sync(0xFFFFFFFFu, acc, 16);   // combine d-halves
                acc *= 0.125f;

                float m = acc;
                m = fmaxf(m, __shfl_xor_sync(0xFFFFFFFFu, m, 1));
                m = fmaxf(m, __shfl_xor_sync(0xFFFFFFFFu, m, 2));
                float e = __expf(acc - m);
                float s = e;
                s += __shfl_xor_sync(0xFFFFFFFFu, s, 1);
                s += __shfl_xor_sync(0xFFFFFFFFu, s, 2);
                if (h == 0) ps[96 + idx] = e / s;
            }
        }
        __syncthreads();   // ps visible

        // ---- AV phase: warp w owns window positions {4w..4w+3} ----
        {
            const int w    = tid >> 5;
            const int lane = tid & 31;
            const int c4   = lane & 15;
            const int pp   = lane >> 4;          // 0/1
            const float W0 = wmix[0], W1 = wmix[1], W2 = wmix[2];

            const int pos_e = 4 * w + 2 * pp;    // even position handled by this thread
            const int pos_o = pos_e + 1;         // odd position

            float4* o4 = (float4*)out + (size_t)tile * 256;

            float ax, ay, az, aw;                // accumulator for pos_e
            {
                // g0 window rows, shared by the whole warp (broadcast loads)
                float4 R0 = vsb[(4 * w + 0) * 16 + c4];
                float4 R1 = vsb[(4 * w + 1) * 16 + c4];
                float4 R2 = vsb[(4 * w + 2) * 16 + c4];
                float4 R3 = vsb[(4 * w + 3) * 16 + c4];

                // ---- odd position: group0 only; store immediately, free regs ----
                {
                    float4 pa = *(const float4*)(ps + 4 * pos_o);
                    float sx = pa.x * R0.x, sy = pa.x * R0.y, sz = pa.x * R0.z, sw = pa.x * R0.w;
                    sx = fmaf(pa.y, R1.x, sx); sy = fmaf(pa.y, R1.y, sy);
                    sz = fmaf(pa.y, R1.z, sz); sw = fmaf(pa.y, R1.w, sw);
                    sx = fmaf(pa.z, R2.x, sx); sy = fmaf(pa.z, R2.y, sy);
                    sz = fmaf(pa.z, R2.z, sz); sw = fmaf(pa.z, R2.w, sw);
                    sx = fmaf(pa.w, R3.x, sx); sy = fmaf(pa.w, R3.y, sy);
                    sz = fmaf(pa.w, R3.z, sz); sw = fmaf(pa.w, R3.w, sw);
                    float4 r; r.x = W0 * sx; r.y = W0 * sy; r.z = W0 * sz; r.w = W0 * sw;
                    __stcs(&o4[pos_o * 16 + c4], r);
                }

                // ---- even position g0 ----
                {
                    float4 pa = *(const float4*)(ps + 4 * pos_e);
                    float sx = pa.x * R0.x, sy = pa.x * R0.y, sz = pa.x * R0.z, sw = pa.x * R0.w;
                    sx = fmaf(pa.y, R1.x, sx); sy = fmaf(pa.y, R1.y, sy);
                    sz = fmaf(pa.y, R1.z, sz); sw = fmaf(pa.y, R1.w, sw);
                    sx = fmaf(pa.z, R2.x, sx); sy = fmaf(pa.z, R2.y, sy);
                    sz = fmaf(pa.z, R2.z, sz); sw = fmaf(pa.z, R2.w, sw);
                    sx = fmaf(pa.w, R3.x, sx); sy = fmaf(pa.w, R3.y, sy);
                    sz = fmaf(pa.w, R3.z, sz); sw = fmaf(pa.w, R3.w, sw);
                    ax = W0 * sx; ay = W0 * sy; az = W0 * sz; aw = W0 * sw;
                }

                // ---- even position g1: rows 8*win + {0,2,4,6}; R0/R2 cover two ----
                {
                    const int win   = w >> 1;
                    const int inst1 = win * 4 + ((pos_e >> 1) & 3);
                    float4 pb = *(const float4*)(ps + 64 + 4 * inst1);
                    const int eoff = (w & 1) ? 0 : 4;   // odd w -> {0,2}, even w -> {4,6}
                    float4 E0 = vsb[(8 * win + eoff + 0) * 16 + c4];
                    float4 E1 = vsb[(8 * win + eoff + 2) * 16 + c4];
                    float c0_, c1_, c2_, c3_;           // j->register map
                    if ((w & 1) == 0) { c0_ = pb.x; c1_ = pb.y; c2_ = pb.z; c3_ = pb.w; }
                    else              { c2_ = pb.x; c3_ = pb.y; c0_ = pb.z; c1_ = pb.w; }
                    float sx = c0_ * R0.x, sy = c0_ * R0.y, sz = c0_ * R0.z, sw = c0_ * R0.w;
                    sx = fmaf(c1_, R2.x, sx); sy = fmaf(c1_, R2.y, sy);
                    sz = fmaf(c1_, R2.z, sz); sw = fmaf(c1_, R2.w, sw);
                    sx = fmaf(c2_, E0.x, sx); sy = fmaf(c2_, E0.y, sy);
                    sz = fmaf(c2_, E0.z, sz); sw = fmaf(c2_, E0.w, sw);
                    sx = fmaf(c3_, E1.x, sx); sy = fmaf(c3_, E1.y, sy);
                    sz = fmaf(c3_, E1.z, sz); sw = fmaf(c3_, E1.w, sw);
                    ax = fmaf(W1, sx, ax); ay = fmaf(W1, sy, ay);
                    az = fmaf(W1, sz, az); aw = fmaf(W1, sw, aw);
                }
            }   // R0..R3 dead here

            // ---- even position g2 (only pp==0, pos_e == 4w): rows {0,4,8,12} ----
            if (pp == 0) {
                float4 pc = *(const float4*)(ps + 96 + 4 * w);
                float4 G0 = vsb[ 0 * 16 + c4];
                float4 G1 = vsb[ 4 * 16 + c4];
                float4 G2 = vsb[ 8 * 16 + c4];
                float4 G3 = vsb[12 * 16 + c4];
                float sx = pc.x * G0.x, sy = pc.x * G0.y, sz = pc.x * G0.z, sw = pc.x * G0.w;
                sx = fmaf(pc.y, G1.x, sx); sy = fmaf(pc.y, G1.y, sy);
                sz = fmaf(pc.y, G1.z, sz); sw = fmaf(pc.y, G1.w, sw);
                sx = fmaf(pc.z, G2.x, sx); sy = fmaf(pc.z, G2.y, sy);
                sz = fmaf(pc.z, G2.z, sz); sw = fmaf(pc.z, G2.w, sw);
                sx = fmaf(pc.w, G3.x, sx); sy = fmaf(pc.w, G3.y, sy);
                sz = fmaf(pc.w, G3.z, sz); sw = fmaf(pc.w, G3.w, sw);
                ax = fmaf(W2, sx, ax); ay = fmaf(W2, sy, ay);
                az = fmaf(W2, sz, az); aw = fmaf(W2, sw, aw);
            }

            float4 r; r.x = ax; r.y = ay; r.z = az; r.w = aw;
            __stcs(&o4[pos_e * 16 + c4], r);
        }

        cur ^= 1;
    }
}

extern "C" void kernel_launch(void* const* d_in, const int* in_sizes, int n_in,
                              void* d_out, int out_size)
{
    const float* q     = (const float*)d_in[0];
    const float* k     = (const float*)d_in[1];
    const float* v     = (const float*)d_in[2];
    const float* alpha = (const float*)d_in[3];
    float* out         = (float*)d_out;

    int n_tiles = in_sizes[0] / 1024;   // 16384 superblocks
    dilated_attn_kernel<<<GRID, TPB>>>(q, k, v, alpha, out, n_tiles);
}